// round 8
// baseline (speedup 1.0000x reference)
#include <cuda_runtime.h>
#include <cuda_bf16.h>

#define T_DIM    2048
#define NUM_SEG  64
#define SEG      32
#define F_DIM    32
#define H_DIM    128
#define FEAT_DIM 4

#define SP_PITCH 12

// Precomputed Wh = h @ W_w^T + W_b  (2048 x 32), produced by wh_kernel,
// consumed by the attention kernel (stream-ordered; no cross-block sync).
__device__ float g_Wh[T_DIM * F_DIM];

// ---------------------------------------------------------------------------
// Kernel 1: Wh. 128 blocks x 256 threads; 16 rows/block, 2 rows/warp.
// W staged coalesced into smem; inner loop is conflict-free LDS.128.
// ---------------------------------------------------------------------------
__global__ __launch_bounds__(256, 2)
void wh_kernel(const float* __restrict__ h,
               const float* __restrict__ W_w,
               const float* __restrict__ W_b)
{
    __shared__ float4 Wq_s[F_DIM][33];      // 16.5 KB: W row ff as float4 chunks
    __shared__ float4 hr_s[16][32];         // 8 KB: this block's 16 h rows

    const int tid  = threadIdx.x;
    const int blk  = blockIdx.x;
    const int row0 = blk * 16;

    const int warp = tid >> 5;              // 0..7
    const int lane = tid & 31;

    // Stage W (4096 float4 / 256 thr = 4 iters each, wait 32*32=1024 float4)
    {
        const float4* w4 = reinterpret_cast<const float4*>(W_w);
        const float4* h4 = reinterpret_cast<const float4*>(h + (size_t)row0 * H_DIM);
        #pragma unroll
        for (int n = tid; n < F_DIM * (H_DIM / 4); n += 256)      // 1024 -> 4 iters
            Wq_s[n >> 5][n & 31] = w4[n];
        #pragma unroll
        for (int n = tid; n < 16 * (H_DIM / 4); n += 256)         // 512 -> 2 iters
            hr_s[n >> 5][n & 31] = h4[n];
    }
    __syncthreads();

    // warp -> rows {warp, warp+8}; lane = output col ff
    const float bias = W_b[lane];
    float acc0 = bias, acc1 = bias;
    #pragma unroll 8
    for (int k4 = 0; k4 < H_DIM / 4; k4++) {
        const float4 w  = Wq_s[lane][k4];   // per-lane LDS.128, conflict-free
        const float4 a0 = hr_s[warp][k4];       // broadcast
        const float4 a1 = hr_s[warp + 8][k4];   // broadcast
        acc0 += a0.x * w.x + a0.y * w.y + a0.z * w.z + a0.w * w.w;
        acc1 += a1.x * w.x + a1.y * w.y + a1.z * w.z + a1.w * w.w;
    }
    g_Wh[(size_t)(row0 + warp)     * F_DIM + lane] = acc0;   // 128B per warp, coalesced
    g_Wh[(size_t)(row0 + warp + 8) * F_DIM + lane] = acc1;
}

// ---------------------------------------------------------------------------
// Kernel 2: attention. 256 blocks x 256 threads; 8 rows/block (1 row/warp),
// 4 blocks/segment, 2 blocks/SM. No W staging, no Wh matmul.
// ---------------------------------------------------------------------------
__global__ __launch_bounds__(256, 2)
void horizon_attn_kernel(const float* __restrict__ f,
                         const float* __restrict__ h,
                         const float* __restrict__ features,
                         const float* __restrict__ hor,
                         float* __restrict__ S)
{
    __shared__ float4 h4_s[SEG][32];          // 16 KB   h_seg rows as float4
    __shared__ float4 Wh4_s[SEG][9];          // 4.6 KB  Wh rows, pitch 9 f4
    __shared__ float  sp[8][SEG][SP_PITCH];   // 12 KB   per-warp logit partials

    const int tid  = threadIdx.x;
    const int blk  = blockIdx.x;
    const int seg0 = (blk >> 2) * SEG;

    const int warp = tid >> 5;                // 0..7
    const int lane = tid & 31;

    const int i  = blk * 8 + warp;            // global output row
    const int gj = seg0 + lane;               // lane's segment column

    // ===== Phase 0: issue all DRAM loads early =============================
    float4 fv[8];
    {
        const float4* fblk = reinterpret_cast<const float4*>(
            f + ((size_t)i * T_DIM + seg0) * F_DIM);
        #pragma unroll
        for (int m = 0; m < 8; m++)
            fv[m] = fblk[m * 32 + lane];      // 4KB contiguous: 4 lines per LDG
    }
    const size_t mb = (size_t)i * T_DIM + gj;
    const float bearing = hor[mb];
    const float dist    = features[mb * FEAT_DIM];

    // ===== Phase 1: stage h_seg (16 KB) + Wh block (2 KB from L2) ==========
    {
        const float4* h4 = reinterpret_cast<const float4*>(h + (size_t)seg0 * H_DIM);
        #pragma unroll
        for (int n = tid; n < SEG * (H_DIM / 4); n += 256)        // 1024 -> 4 iters
            h4_s[n >> 5][n & 31] = h4[n];

        // Wh: 32 rows x 8 float4 = 256 float4; one per thread
        const float4 v = __ldcg(reinterpret_cast<const float4*>(g_Wh)
                                + (size_t)seg0 * (F_DIM / 4) + tid);
        Wh4_s[tid >> 3][tid & 7] = v;
    }
    __syncthreads();

    // ===== Phase 3: partial logit dots + per-warp redistribution ===========
    float* spw = &sp[warp][0][0];
    {
        const int g = lane >> 3;              // 0..3
        const int c = lane & 7;               // chunk 0..7
        #pragma unroll
        for (int m = 0; m < 8; m++) {
            const int j = 4 * m + g;
            const float4 w = Wh4_s[j][c];
            const float4 a = fv[m];
            spw[j * SP_PITCH + c] =
                a.x * w.x + a.y * w.y + a.z * w.z + a.w * w.w;
        }
    }
    __syncwarp();
    const float4 A = *reinterpret_cast<const float4*>(spw + lane * SP_PITCH);
    const float4 B = *reinterpret_cast<const float4*>(spw + lane * SP_PITCH + 4);
    const float logit = (A.x + A.y + A.z + A.w) + (B.x + B.y + B.z + B.w);

    const bool bad = (bearing < 0.f) || (dist > 10.f) || (i == gj);
    const float val = bad ? -1000.f : logit;

    // ===== Phase 4: warp softmax ===========================================
    float mx = val;
    #pragma unroll
    for (int off = 16; off; off >>= 1)
        mx = fmaxf(mx, __shfl_xor_sync(0xFFFFFFFFu, mx, off));
    const float e = expf(val - mx);
    float ssum = e;
    #pragma unroll
    for (int off = 16; off; off >>= 1)
        ssum += __shfl_xor_sync(0xFFFFFFFFu, ssum, off);
    const float attn = e / ssum;

    // ===== Phase 5: S[i,:] = sum_j attn_j * h_seg[j,:] =====================
    float4 Acc = make_float4(0.f, 0.f, 0.f, 0.f);
    #pragma unroll
    for (int jj = 0; jj < SEG; jj++) {
        const float a = __shfl_sync(0xFFFFFFFFu, attn, jj);
        const float4 hv = h4_s[jj][lane];     // conflict-free LDS.128
        Acc.x += a * hv.x;  Acc.y += a * hv.y;
        Acc.z += a * hv.z;  Acc.w += a * hv.w;
    }
    reinterpret_cast<float4*>(S + (size_t)i * H_DIM)[lane] = Acc;  // STG.128
}

extern "C" void kernel_launch(void* const* d_in, const int* in_sizes, int n_in,
                              void* d_out, int out_size)
{
    // metadata order: f, h, features, hor_bearings_MTX, W_w, W_b, sub_batches
    const float* f        = (const float*)d_in[0];
    const float* h        = (const float*)d_in[1];
    const float* features = (const float*)d_in[2];
    const float* hor      = (const float*)d_in[3];
    const float* W_w      = (const float*)d_in[4];
    const float* W_b      = (const float*)d_in[5];
    float* S = (float*)d_out;

    wh_kernel<<<T_DIM / 16, 256>>>(h, W_w, W_b);
    horizon_attn_kernel<<<T_DIM / 8, 256>>>(f, h, features, hor, S);
}

// round 10
// speedup vs baseline: 1.0208x; 1.0208x over previous
#include <cuda_runtime.h>
#include <cuda_bf16.h>
#include <cstdint>

#define T_DIM    2048
#define NUM_SEG  64
#define SEG      32
#define F_DIM    32
#define H_DIM    128
#define FEAT_DIM 4

// Precomputed Wh = h @ W_w^T + W_b  (2048 x 32), produced by wh_kernel.
__device__ float g_Wh[T_DIM * F_DIM];

__device__ __forceinline__ uint32_t smem_u32(const void* p) {
    uint32_t a;
    asm("{ .reg .u64 t; cvta.to.shared.u64 t, %1; cvt.u32.u64 %0, t; }" : "=r"(a) : "l"(p));
    return a;
}

__device__ __forceinline__ void bulk_g2s(uint32_t dst, const void* src, uint32_t bytes, uint32_t mbar) {
    asm volatile(
        "cp.async.bulk.shared::cta.global.mbarrier::complete_tx::bytes [%0], [%1], %2, [%3];"
        :: "r"(dst), "l"(src), "r"(bytes), "r"(mbar) : "memory");
}

__device__ __forceinline__ void mbar_wait0(uint32_t mbar) {
    uint32_t done = 0;
    while (!done) {
        asm volatile(
            "{\n\t.reg .pred p;\n\t"
            "mbarrier.try_wait.parity.acquire.cta.shared::cta.b64 p, [%1], 0, 0x989680;\n\t"
            "selp.b32 %0, 1, 0, p;\n\t}"
            : "=r"(done) : "r"(mbar) : "memory");
    }
}

// ---------------------------------------------------------------------------
// Kernel 1: Wh. 128 blocks x 256 threads; 16 rows/block, 2 rows/warp.
// ---------------------------------------------------------------------------
__global__ __launch_bounds__(256, 2)
void wh_kernel(const float* __restrict__ h,
               const float* __restrict__ W_w,
               const float* __restrict__ W_b)
{
    __shared__ float4 Wq_s[F_DIM][33];      // 16.5 KB
    __shared__ float4 hr_s[16][32];         // 8 KB

    const int tid  = threadIdx.x;
    const int row0 = blockIdx.x * 16;
    const int warp = tid >> 5;
    const int lane = tid & 31;

    {
        const float4* w4 = reinterpret_cast<const float4*>(W_w);
        const float4* h4 = reinterpret_cast<const float4*>(h + (size_t)row0 * H_DIM);
        #pragma unroll
        for (int n = tid; n < F_DIM * (H_DIM / 4); n += 256)
            Wq_s[n >> 5][n & 31] = w4[n];
        #pragma unroll
        for (int n = tid; n < 16 * (H_DIM / 4); n += 256)
            hr_s[n >> 5][n & 31] = h4[n];
    }
    __syncthreads();

    const float bias = W_b[lane];
    float acc0 = bias, acc1 = bias;
    #pragma unroll 8
    for (int k4 = 0; k4 < H_DIM / 4; k4++) {
        const float4 w  = Wq_s[lane][k4];
        const float4 a0 = hr_s[warp][k4];
        const float4 a1 = hr_s[warp + 8][k4];
        acc0 += a0.x * w.x + a0.y * w.y + a0.z * w.z + a0.w * w.w;
        acc1 += a1.x * w.x + a1.y * w.y + a1.z * w.z + a1.w * w.w;
    }
    g_Wh[(size_t)(row0 + warp)     * F_DIM + lane] = acc0;
    g_Wh[(size_t)(row0 + warp + 8) * F_DIM + lane] = acc1;
}

// ---------------------------------------------------------------------------
// Kernel 2: attention. 512 blocks x 128 threads; 4 rows/block (1 row/warp).
// All heavy data lands in smem via cp.async.bulk (zero register pressure,
// hardware MLP). Logit reduction via shuffles, no smem scratch.
// ---------------------------------------------------------------------------
__global__ __launch_bounds__(128, 4)
void horizon_attn_kernel(const float* __restrict__ f,
                         const float* __restrict__ h,
                         const float* __restrict__ features,
                         const float* __restrict__ hor,
                         float* __restrict__ S)
{
    __shared__ float4 fs[4][SEG][8];        // 16 KB: 4 f row-blocks, linear
    __shared__ float4 h4_s[SEG][32];        // 16 KB: h_seg
    __shared__ float4 Wh4_s[SEG][8];        // 4 KB : Wh segment rows
    __shared__ alignas(8) unsigned long long mbar;

    const int tid  = threadIdx.x;
    const int blk  = blockIdx.x;
    const int seg0 = (blk >> 3) * SEG;      // 8 blocks per segment

    const int warp = tid >> 5;              // 0..3
    const int lane = tid & 31;

    const int i  = blk * 4 + warp;          // global output row
    const int gj = seg0 + lane;             // lane's segment column

    // ---- mbarrier init + bulk copies (issued by thread 0) ----
    const uint32_t mb_a = smem_u32(&mbar);
    if (tid == 0) {
        asm volatile("mbarrier.init.shared.b64 [%0], 1;" :: "r"(mb_a) : "memory");
    }
    __syncthreads();
    if (tid == 0) {
        // f: 4 x 4096 B, h_seg: 16384 B, Wh: SEG*F_DIM*4 = 4096 B
        const uint32_t total = 4 * 4096 + 16384 + 4096;   // 36864 B
        asm volatile("mbarrier.arrive.expect_tx.shared.b64 _, [%0], %1;"
                     :: "r"(mb_a), "r"(total) : "memory");
        #pragma unroll
        for (int r = 0; r < 4; r++)
            bulk_g2s(smem_u32(&fs[r][0][0]),
                     f + ((size_t)(blk * 4 + r) * T_DIM + seg0) * F_DIM,
                     4096, mb_a);
        bulk_g2s(smem_u32(&h4_s[0][0]),  h + (size_t)seg0 * H_DIM, 16384, mb_a);
        bulk_g2s(smem_u32(&Wh4_s[0][0]), g_Wh + (size_t)seg0 * F_DIM, 4096, mb_a);
    }

    // ---- overlap: per-lane mask loads (tiny, independent of smem) ----
    const size_t mbi = (size_t)i * T_DIM + gj;
    const float bearing = hor[mbi];
    const float dist    = features[mbi * FEAT_DIM];
    const float badf = ((bearing < 0.f) || (dist > 10.f) || (i == gj)) ? 1.f : 0.f;

    // ---- wait for all bulk data ----
    mbar_wait0(mb_a);

    // ---- partial logit dots: lane l -> chunk c=l&7 of row j=4m+(l>>3) ----
    const int g = lane >> 3;
    const int c = lane & 7;
    float val[8];
    #pragma unroll
    for (int m = 0; m < 8; m++) {
        const int j = 4 * m + g;
        const float4 a = fs[warp][j][c];    // 128B contiguous per 8-lane phase
        const float4 w = Wh4_s[j][c];       // 128B contiguous per 8-lane phase
        float p = a.x * w.x + a.y * w.y + a.z * w.z + a.w * w.w;
        // 8-lane butterfly: lanes 8g..8g+7 all get logit[j]
        p += __shfl_xor_sync(0xFFFFFFFFu, p, 1);
        p += __shfl_xor_sync(0xFFFFFFFFu, p, 2);
        p += __shfl_xor_sync(0xFFFFFFFFu, p, 4);
        // fetch bad flag for column j (lives in lane j)
        const float bm = __shfl_sync(0xFFFFFFFFu, badf, j);
        val[m] = (bm != 0.f) ? -1000.f : p;
    }

    // ---- softmax over 32 columns (each column replicated on 8 lanes) ----
    float mx = val[0];
    #pragma unroll
    for (int m = 1; m < 8; m++) mx = fmaxf(mx, val[m]);
    #pragma unroll
    for (int off = 16; off; off >>= 1)
        mx = fmaxf(mx, __shfl_xor_sync(0xFFFFFFFFu, mx, off));

    float e[8];
    float ls = 0.f;
    #pragma unroll
    for (int m = 0; m < 8; m++) { e[m] = expf(val[m] - mx); ls += e[m]; }
    #pragma unroll
    for (int off = 16; off; off >>= 1)
        ls += __shfl_xor_sync(0xFFFFFFFFu, ls, off);
    // ls = 8 * true_sum (each column counted by its 8 holder lanes)
    const float inv = 8.f / ls;
    #pragma unroll
    for (int m = 0; m < 8; m++) e[m] *= inv;   // e[m] = attn[4m+g]

    // ---- S[i,:] = sum_j attn_j * h_seg[j,:]; lane owns 4 contiguous cols ----
    float4 Acc = make_float4(0.f, 0.f, 0.f, 0.f);
    #pragma unroll
    for (int jj = 0; jj < SEG; jj++) {
        // attn[jj] = e[jj>>2] on lanes with g = jj&3, e.g. lane (jj&3)*8
        const float a = __shfl_sync(0xFFFFFFFFu, e[jj >> 2], (jj & 3) * 8);
        const float4 hv = h4_s[jj][lane];
        Acc.x += a * hv.x;  Acc.y += a * hv.y;
        Acc.z += a * hv.z;  Acc.w += a * hv.w;
    }
    reinterpret_cast<float4*>(S + (size_t)i * H_DIM)[lane] = Acc;
}

extern "C" void kernel_launch(void* const* d_in, const int* in_sizes, int n_in,
                              void* d_out, int out_size)
{
    // metadata order: f, h, features, hor_bearings_MTX, W_w, W_b, sub_batches
    const float* f        = (const float*)d_in[0];
    const float* h        = (const float*)d_in[1];
    const float* features = (const float*)d_in[2];
    const float* hor      = (const float*)d_in[3];
    const float* W_w      = (const float*)d_in[4];
    const float* W_b      = (const float*)d_in[5];
    float* S = (float*)d_out;

    wh_kernel<<<T_DIM / 16, 256>>>(h, W_w, W_b);
    horizon_attn_kernel<<<T_DIM / 4, 128>>>(f, h, features, hor, S);
}